// round 15
// baseline (speedup 1.0000x reference)
#include <cuda_runtime.h>
#include <cstdint>

#define NMAX 50000
#define EMAX 800000
#define KB 8          // branches
#define CI 32
#define CO 32
#define CM 36         // C_IN + 4
#define TS 36         // h-tile row stride (floats)
#define PNT 36        // precompute n-tiles: 8 branches*4 + skip*4

// scratch (device globals; allocation is forbidden).
// g_acc / g_cnt / g_bcnt are BSS-zeroed at module load and then self-cleaned
// by k_finalize at the end of every launch -> no zeroing kernel needed.
__device__ float    g_acc[NMAX * CO];        // per-node accumulated edge features
__device__ float    g_skip[NMAX * CO];       // x @ Wr (br folded into finalize)
__device__ float    g_p[KB * NMAX * CO];     // per-branch x @ W1a
__device__ int      g_cnt[NMAX];             // in-degree
__device__ uint32_t g_sdp[KB * EMAX];        // packed {s:16, d:16} per branch slot
__device__ float4   g_eab[KB * EMAX];        // edge_attr per branch slot
__device__ float    g_ewb[KB * EMAX];        // edge_weight per branch slot
__device__ int      g_bcnt[KB];

// ---------------------------------------------------------------------------
// helpers: bf16 hi/lo split + bf16 mma
// ---------------------------------------------------------------------------
__device__ __forceinline__ void split2(float x0, float x1,
                                       uint32_t& hi, uint32_t& lo) {
    uint32_t h;
    asm("cvt.rn.bf16x2.f32 %0, %1, %2;" : "=r"(h) : "f"(x1), "f"(x0)); // lo=x0
    const float h0 = __uint_as_float(h << 16);
    const float h1 = __uint_as_float(h & 0xffff0000u);
    const float l0 = x0 - h0;
    const float l1 = x1 - h1;
    uint32_t l;
    asm("cvt.rn.bf16x2.f32 %0, %1, %2;" : "=r"(l) : "f"(l1), "f"(l0));
    hi = h; lo = l;
}
__device__ __forceinline__ void mma_bf16(float c[4], const uint32_t a[4],
                                         const uint32_t b[2]) {
    asm volatile(
        "mma.sync.aligned.m16n8k16.row.col.f32.bf16.bf16.f32 "
        "{%0,%1,%2,%3}, {%4,%5,%6,%7}, {%8,%9}, {%0,%1,%2,%3};"
        : "+f"(c[0]), "+f"(c[1]), "+f"(c[2]), "+f"(c[3])
        : "r"(a[0]), "r"(a[1]), "r"(a[2]), "r"(a[3]), "r"(b[0]), "r"(b[1]));
}

// ---------------------------------------------------------------------------
// Kernel 1: classify edges into 8 branches, 2 edges per thread for MLP on
// the random pos gathers. Block-aggregated counting sort, SoA records,
// in-degree counts.
// ---------------------------------------------------------------------------
__global__ void __launch_bounds__(256) k_classify(
    const float* __restrict__ pos,
    const int* __restrict__ ei,
    const float* __restrict__ ea,
    const float* __restrict__ ew,
    int E)
{
    __shared__ int s_cnt[KB];
    __shared__ int s_base[KB];
    const int t = threadIdx.x;
    if (t < KB) s_cnt[t] = 0;
    __syncthreads();

    const int e0 = blockIdx.x * 512 + t;        // first edge
    const int e1 = e0 + 256;                    // second edge

    int k0 = 0, r0 = 0, s0 = 0, d0 = 0;
    int k1 = 0, r1 = 0, s1 = 0, d1 = 0;
    float4 a0 = make_float4(0.f, 0.f, 0.f, 0.f);
    float4 a1 = make_float4(0.f, 0.f, 0.f, 0.f);
    float w0 = 0.f, w1 = 0.f;

    // batched loads for both edges (independent chains -> MLP)
    float2 ps0, pd0, ps1, pd1;
    const bool v0 = (e0 < E), v1 = (e1 < E);
    if (v0) {
        s0 = ei[e0]; d0 = ei[E + e0];
        ps0 = reinterpret_cast<const float2*>(pos)[s0];
        pd0 = reinterpret_cast<const float2*>(pos)[d0];
        a0 = reinterpret_cast<const float4*>(ea)[e0];
        w0 = ew[e0];
    }
    if (v1) {
        s1 = ei[e1]; d1 = ei[E + e1];
        ps1 = reinterpret_cast<const float2*>(pos)[s1];
        pd1 = reinterpret_cast<const float2*>(pos)[d1];
        a1 = reinterpret_cast<const float4*>(ea)[e1];
        w1 = ew[e1];
    }
    if (v0) {
        const float dx = ps0.x - pd0.x, dy = ps0.y - pd0.y;
        k0 = (dx > 0.0f ? 1 : 0) + (dy > 0.0f ? 2 : 0)
           + ((fabsf(dx) - fabsf(dy)) > 0.0f ? 4 : 0);
        r0 = atomicAdd(&s_cnt[k0], 1);
        atomicAdd(&g_cnt[d0], 1);
    }
    if (v1) {
        const float dx = ps1.x - pd1.x, dy = ps1.y - pd1.y;
        k1 = (dx > 0.0f ? 1 : 0) + (dy > 0.0f ? 2 : 0)
           + ((fabsf(dx) - fabsf(dy)) > 0.0f ? 4 : 0);
        r1 = atomicAdd(&s_cnt[k1], 1);
        atomicAdd(&g_cnt[d1], 1);
    }
    __syncthreads();
    if (t < KB) s_base[t] = atomicAdd(&g_bcnt[t], s_cnt[t]);
    __syncthreads();
    if (v0) {
        const int slot = k0 * EMAX + s_base[k0] + r0;
        g_sdp[slot] = ((uint32_t)s0 << 16) | (uint32_t)d0;
        g_eab[slot] = a0;
        g_ewb[slot] = w0;
    }
    if (v1) {
        const int slot = k1 * EMAX + s_base[k1] + r1;
        g_sdp[slot] = ((uint32_t)s1 << 16) | (uint32_t)d1;
        g_eab[slot] = a1;
        g_ewb[slot] = w1;
    }
}

// ---------------------------------------------------------------------------
// Kernel 2: tensor-core precompute: [p0..p7 | skip] = x @ [W1a_0..W1a_7 | Wr]
// ---------------------------------------------------------------------------
__global__ void __launch_bounds__(256) k_precompute_mma(
    const float* __restrict__ x,
    const float* __restrict__ W1,
    const float* __restrict__ Wr,
    int N)
{
    __shared__ uint32_t s_B[PNT * 2 * 32 * 4];   // 36 KB

    for (int idx = threadIdx.x; idx < PNT * 2 * 32; idx += blockDim.x) {
        const int lane = idx & 31, ks = (idx >> 5) & 1, nt = idx >> 6;
        const int cg = lane >> 2, r2 = (lane & 3) * 2;
        const float* src;
        if (nt < 32) src = W1 + ((size_t)(nt >> 2) * CM) * CO + (nt & 3) * 8 + cg;
        else         src = Wr + (nt - 32) * 8 + cg;
        const int r0 = ks * 16 + r2;
        uint32_t h0, l0, h1, l1;
        split2(src[(r0    ) * CO], src[(r0 + 1) * CO], h0, l0);
        split2(src[(r0 + 8) * CO], src[(r0 + 9) * CO], h1, l1);
        uint32_t* dst = &s_B[idx * 4];
        dst[0] = h0; dst[1] = h1; dst[2] = l0; dst[3] = l1;
    }
    __syncthreads();

    const int lane = threadIdx.x & 31;
    const int gid = lane >> 2, tig = lane & 3;
    const int wid = blockIdx.x * (blockDim.x >> 5) + (threadIdx.x >> 5);
    const int nwarp = gridDim.x * (blockDim.x >> 5);
    const int ntile = (N + 31) >> 5;

    for (int tile = wid; tile < ntile; tile += nwarp) {
        const int n0 = (tile << 5) + gid;

        uint32_t Ah[2][2][4], Al[2][2][4];
#pragma unroll
        for (int mt = 0; mt < 2; mt++) {
            const int na = min(n0 + mt * 16, N - 1);
            const int nb = min(n0 + mt * 16 + 8, N - 1);
#pragma unroll
            for (int ks = 0; ks < 2; ks++) {
                const int c0 = ks * 16 + tig * 2;
                float2 v0 = *reinterpret_cast<const float2*>(x + (size_t)na * CI + c0);
                float2 v1 = *reinterpret_cast<const float2*>(x + (size_t)nb * CI + c0);
                float2 v2 = *reinterpret_cast<const float2*>(x + (size_t)na * CI + c0 + 8);
                float2 v3 = *reinterpret_cast<const float2*>(x + (size_t)nb * CI + c0 + 8);
                split2(v0.x, v0.y, Ah[mt][ks][0], Al[mt][ks][0]);
                split2(v1.x, v1.y, Ah[mt][ks][1], Al[mt][ks][1]);
                split2(v2.x, v2.y, Ah[mt][ks][2], Al[mt][ks][2]);
                split2(v3.x, v3.y, Ah[mt][ks][3], Al[mt][ks][3]);
            }
        }

#pragma unroll
        for (int nt = 0; nt < PNT; nt++) {
            float c[2][4] = {{0.f,0.f,0.f,0.f},{0.f,0.f,0.f,0.f}};
#pragma unroll
            for (int ks = 0; ks < 2; ks++) {
                const uint4 bq = *reinterpret_cast<const uint4*>(
                    &s_B[((nt * 2 + ks) * 32 + lane) * 4]);
                uint32_t bh[2] = {bq.x, bq.y};
                uint32_t bl[2] = {bq.z, bq.w};
#pragma unroll
                for (int mt = 0; mt < 2; mt++) {
                    mma_bf16(c[mt], Ah[mt][ks], bh);
                    mma_bf16(c[mt], Al[mt][ks], bh);
                    mma_bf16(c[mt], Ah[mt][ks], bl);
                }
            }
            float* base;
            int ch;
            if (nt < 32) { base = g_p + (size_t)(nt >> 2) * N * CO; ch = (nt & 3) * 8 + tig * 2; }
            else         { base = g_skip;                            ch = (nt - 32) * 8 + tig * 2; }
#pragma unroll
            for (int mt = 0; mt < 2; mt++) {
                const int na = n0 + mt * 16;
                if (na < N)
                    *reinterpret_cast<float2*>(base + (size_t)na * CO + ch) =
                        make_float2(c[mt][0], c[mt][1]);
                if (na + 8 < N)
                    *reinterpret_cast<float2*>(base + (size_t)(na + 8) * CO + ch) =
                        make_float2(c[mt][2], c[mt][3]);
            }
        }
    }
}

// ---------------------------------------------------------------------------
// Kernel 3: warp-tile edge MLP (proven round-8/12 variant, FROZEN:
// 128 regs x 128 thr x 4 blocks = full RF; any register add drops a block).
// ---------------------------------------------------------------------------
#define WPB 4   // warps per block
__global__ void __launch_bounds__(32 * WPB, 4) k_edge_mlp(
    const float* __restrict__ W1,
    const float* __restrict__ b1,
    const float* __restrict__ W2,
    const float* __restrict__ b2,
    int N)
{
    const int k    = blockIdx.y;
    const int lane = threadIdx.x & 31;
    const int w    = threadIdx.x >> 5;

    __shared__ float  s_h[WPB][32][TS];    // h tile / C transpose buffer
    __shared__ float4 s_ea[WPB][32];
    __shared__ float  s_ew[WPB][32];
    __shared__ int    s_d[WPB][32];

    // ---- per-lane layer-1 tail weights (channels j*4..j*4+3) ----
    const int j = lane & 7;
    float4 w1b[4];
#pragma unroll
    for (int q = 0; q < 4; q++)
        w1b[q] = *reinterpret_cast<const float4*>(
            W1 + ((size_t)k * CM + 32 + q) * CO + j * 4);
    const float4 b1v = *reinterpret_cast<const float4*>(b1 + k * CO + j * 4);

    // ---- B fragments (W2), bf16 hi/lo, register-resident ----
    uint32_t Bh[4][2][2], Bl[4][2][2];
    {
        const int col = lane >> 2;
        const int r2  = (lane & 3) * 2;
        const float* W2k = W2 + (size_t)k * CO * CO;
#pragma unroll
        for (int nt = 0; nt < 4; nt++)
#pragma unroll
            for (int ks = 0; ks < 2; ks++) {
                const int r0 = ks * 16 + r2;
                split2(W2k[(r0    ) * CO + nt * 8 + col],
                       W2k[(r0 + 1) * CO + nt * 8 + col],
                       Bh[nt][ks][0], Bl[nt][ks][0]);
                split2(W2k[(r0 + 8) * CO + nt * 8 + col],
                       W2k[(r0 + 9) * CO + nt * 8 + col],
                       Bh[nt][ks][1], Bl[nt][ks][1]);
            }
    }
    float2 b2v[4];
#pragma unroll
    for (int nt = 0; nt < 4; nt++)
        b2v[nt] = *reinterpret_cast<const float2*>(
            b2 + k * CO + nt * 8 + 2 * (lane & 3));

    const int cnt = g_bcnt[k];
    const int ntile = (cnt + 31) >> 5;
    const uint32_t* __restrict__ sdp = g_sdp + (size_t)k * EMAX;
    const float4*   __restrict__ eab = g_eab + (size_t)k * EMAX;
    const float*    __restrict__ ewb = g_ewb + (size_t)k * EMAX;
    const float4*   __restrict__ pb =
        reinterpret_cast<const float4*>(g_p + (size_t)k * N * CO);

    const int gwarp = blockIdx.x * WPB + w;
    const int nwarp = gridDim.x * WPB;

    for (int tile = gwarp; tile < ntile; tile += nwarp) {
        const int idx = (tile << 5) + lane;
        int si = 0, di = 0;
        float ewv = 0.f;
        float4 ea = make_float4(0.f, 0.f, 0.f, 0.f);
        if (idx < cnt) {
            const uint32_t p = sdp[idx];
            si = (int)(p >> 16);
            di = (int)(p & 0xffffu);
            ea = eab[idx];
            ewv = ewb[idx];
        }
        s_ea[w][lane] = ea;
        s_ew[w][lane] = ewv;
        s_d[w][lane]  = di;
        __syncwarp();

        // ---- cooperative gather + fused layer 1 ----
        const int g = lane >> 3;
#pragma unroll
        for (int i = 0; i < 8; i++) {
            const int t = i * 4 + g;
            const int ss = __shfl_sync(0xffffffffu, si, t);
            const int dd = __shfl_sync(0xffffffffu, di, t);
            const float4 a  = pb[ss * 8 + j];
            const float4 b  = pb[dd * 8 + j];
            const float4 et = s_ea[w][t];
            float4 h4;
            h4.x = fmaf(et.x, w1b[0].x, fmaf(et.y, w1b[1].x,
                   fmaf(et.z, w1b[2].x, fmaf(et.w, w1b[3].x, b1v.x + a.x - b.x))));
            h4.y = fmaf(et.x, w1b[0].y, fmaf(et.y, w1b[1].y,
                   fmaf(et.z, w1b[2].y, fmaf(et.w, w1b[3].y, b1v.y + a.y - b.y))));
            h4.z = fmaf(et.x, w1b[0].z, fmaf(et.y, w1b[1].z,
                   fmaf(et.z, w1b[2].z, fmaf(et.w, w1b[3].z, b1v.z + a.z - b.z))));
            h4.w = fmaf(et.x, w1b[0].w, fmaf(et.y, w1b[1].w,
                   fmaf(et.z, w1b[2].w, fmaf(et.w, w1b[3].w, b1v.w + a.w - b.w))));
            h4.x = fmaxf(h4.x, 0.f);
            h4.y = fmaxf(h4.y, 0.f);
            h4.z = fmaxf(h4.z, 0.f);
            h4.w = fmaxf(h4.w, 0.f);
            *reinterpret_cast<float4*>(&s_h[w][t][j * 4]) = h4;
        }
        __syncwarp();

        // ---- layer 2: bf16 MMA (2 mt x 4 nt x 2 ks x 3 terms) ----
#pragma unroll
        for (int mt = 0; mt < 2; mt++) {
            const int ra = mt * 16 + (lane >> 2);
            const int rb = ra + 8;
            const int c2 = (lane & 3) * 2;
            uint32_t Ah[2][4], Al[2][4];
#pragma unroll
            for (int ks = 0; ks < 2; ks++) {
                const int k0 = ks * 16 + c2;
                float2 v0 = *reinterpret_cast<const float2*>(&s_h[w][ra][k0]);
                float2 v1 = *reinterpret_cast<const float2*>(&s_h[w][rb][k0]);
                float2 v2 = *reinterpret_cast<const float2*>(&s_h[w][ra][k0 + 8]);
                float2 v3 = *reinterpret_cast<const float2*>(&s_h[w][rb][k0 + 8]);
                split2(v0.x, v0.y, Ah[ks][0], Al[ks][0]);
                split2(v1.x, v1.y, Ah[ks][1], Al[ks][1]);
                split2(v2.x, v2.y, Ah[ks][2], Al[ks][2]);
                split2(v3.x, v3.y, Ah[ks][3], Al[ks][3]);
            }
            const float ewa = s_ew[w][ra];
            const float ewb2 = s_ew[w][rb];
#pragma unroll
            for (int nt = 0; nt < 4; nt++) {
                float c[4] = {0.f, 0.f, 0.f, 0.f};
#pragma unroll
                for (int ks = 0; ks < 2; ks++) {
                    mma_bf16(c, Ah[ks], Bh[nt][ks]);
                    mma_bf16(c, Al[ks], Bh[nt][ks]);
                    mma_bf16(c, Ah[ks], Bl[nt][ks]);
                }
                float2 fa, fb;
                fa.x = fmaxf(c[0] + b2v[nt].x, 0.f) * ewa;
                fa.y = fmaxf(c[1] + b2v[nt].y, 0.f) * ewa;
                fb.x = fmaxf(c[2] + b2v[nt].x, 0.f) * ewb2;
                fb.y = fmaxf(c[3] + b2v[nt].y, 0.f) * ewb2;
                *reinterpret_cast<float2*>(&s_h[w][ra][nt * 8 + c2]) = fa;
                *reinterpret_cast<float2*>(&s_h[w][rb][nt * 8 + c2]) = fb;
            }
        }
        __syncwarp();

        // ---- coalesced scatter: one full edge row per 8 lanes, red.v4 ----
        const int c4 = (lane & 7) * 4;
#pragma unroll
        for (int i = 0; i < 8; i++) {
            const int r = i * 4 + (lane >> 3);
            const float4 v = *reinterpret_cast<const float4*>(&s_h[w][r][c4]);
            float* dst = g_acc + (size_t)s_d[w][r] * CO + c4;
            asm volatile("red.global.add.v4.f32 [%0], {%1, %2, %3, %4};"
                         :: "l"(dst), "f"(v.x), "f"(v.y), "f"(v.z), "f"(v.w)
                         : "memory");
        }
        __syncwarp();
    }
}

// ---------------------------------------------------------------------------
// Kernel 4: out = acc / max(cnt,1) + skip + br, then SELF-CLEAN the scratch
// (g_acc, g_cnt, g_bcnt). Proven round-12 form (1 float4 per thread).
// ---------------------------------------------------------------------------
__global__ void __launch_bounds__(256) k_finalize(
    float* __restrict__ out, const float* __restrict__ br, int N)
{
    const int i = blockIdx.x * blockDim.x + threadIdx.x;   // over N*8 float4s
    if (i >= N * 8) return;
    const int n = i >> 3;
    const float inv = 1.0f / fmaxf((float)g_cnt[n], 1.0f);
    const float4 a = reinterpret_cast<const float4*>(g_acc)[i];
    const float4 s = reinterpret_cast<const float4*>(g_skip)[i];
    const float4 b = reinterpret_cast<const float4*>(br)[i & 7];
    float4 o;
    o.x = fmaf(a.x, inv, s.x + b.x);
    o.y = fmaf(a.y, inv, s.y + b.y);
    o.z = fmaf(a.z, inv, s.z + b.z);
    o.w = fmaf(a.w, inv, s.w + b.w);
    reinterpret_cast<float4*>(out)[i] = o;

    // self-clean for next replay
    reinterpret_cast<float4*>(g_acc)[i] = make_float4(0.f, 0.f, 0.f, 0.f);
    if ((i & 7) == 0) g_cnt[n] = 0;
    if (i < KB) g_bcnt[i] = 0;
}

// ---------------------------------------------------------------------------
// Host launcher
// ---------------------------------------------------------------------------
extern "C" void kernel_launch(void* const* d_in, const int* in_sizes, int n_in,
                              void* d_out, int out_size)
{
    const float* x    = (const float*)d_in[0];   // [N, 32]
    const float* pos  = (const float*)d_in[1];   // [N, 2]
    const int*   ei   = (const int*)  d_in[2];   // [2, E]
    const float* ea   = (const float*)d_in[3];   // [E, 4]
    const float* ew   = (const float*)d_in[4];   // [E]
    const float* W1   = (const float*)d_in[5];   // [8, 36, 32]
    const float* b1   = (const float*)d_in[6];   // [8, 32]
    const float* W2   = (const float*)d_in[7];   // [8, 32, 32]
    const float* b2   = (const float*)d_in[8];   // [8, 32]
    const float* Wr   = (const float*)d_in[9];   // [32, 32]
    const float* br   = (const float*)d_in[10];  // [32]
    float* out = (float*)d_out;

    const int N = in_sizes[0] / CI;
    const int E = in_sizes[4];

    // 1) classify: counting sort into 8 branches, 2 edges/thread
    k_classify<<<(E + 511) / 512, 256>>>(pos, ei, ea, ew, E);

    // 2) tensor-core precompute: p[0..7] and skip in one GEMM
    {
        const int ntile = (N + 31) / 32;
        const int blocks = (ntile + 7) / 8;    // 8 warps per block
        k_precompute_mma<<<blocks, 256>>>(x, W1, Wr, N);
    }

    // 3) warp-tile edge MLP (frozen register-B variant)
    {
        dim3 grid(128, KB);
        k_edge_mlp<<<grid, 32 * WPB>>>(W1, b1, W2, b2, N);
    }

    // 4) mean + skip connection (+ br) + scratch self-clean
    k_finalize<<<(N * 8 + 255) / 256, 256>>>(out, br, N);
}

// round 16
// speedup vs baseline: 1.0541x; 1.0541x over previous
#include <cuda_runtime.h>
#include <cstdint>

#define NMAX 50000
#define EMAX 800000
#define KB 8          // branches
#define CI 32
#define CO 32
#define CM 36         // C_IN + 4
#define TS 36         // h-tile row stride (floats)
#define PNT 36        // precompute n-tiles: 8 branches*4 + skip*4

// scratch (device globals; allocation is forbidden).
// g_acc / g_cnt / g_bcnt are BSS-zeroed at module load and then self-cleaned
// by k_finalize at the end of every launch -> no zeroing kernel needed.
__device__ float    g_acc[NMAX * CO];        // per-node accumulated edge features
__device__ float    g_skip[NMAX * CO];       // x @ Wr (br folded into finalize)
__device__ float    g_p[KB * NMAX * CO];     // per-branch x @ W1a
__device__ int      g_cnt[NMAX];             // in-degree
__device__ uint32_t g_sdp[KB * EMAX];        // packed {s:16, d:16} per branch slot
__device__ float4   g_eab[KB * EMAX];        // edge_attr per branch slot
__device__ float    g_ewb[KB * EMAX];        // edge_weight per branch slot
__device__ int      g_bcnt[KB];

// ---------------------------------------------------------------------------
// helpers: bf16 hi/lo split + bf16 mma
// ---------------------------------------------------------------------------
__device__ __forceinline__ void split2(float x0, float x1,
                                       uint32_t& hi, uint32_t& lo) {
    uint32_t h;
    asm("cvt.rn.bf16x2.f32 %0, %1, %2;" : "=r"(h) : "f"(x1), "f"(x0)); // lo=x0
    const float h0 = __uint_as_float(h << 16);
    const float h1 = __uint_as_float(h & 0xffff0000u);
    const float l0 = x0 - h0;
    const float l1 = x1 - h1;
    uint32_t l;
    asm("cvt.rn.bf16x2.f32 %0, %1, %2;" : "=r"(l) : "f"(l1), "f"(l0));
    hi = h; lo = l;
}
__device__ __forceinline__ void mma_bf16(float c[4], const uint32_t a[4],
                                         const uint32_t b[2]) {
    asm volatile(
        "mma.sync.aligned.m16n8k16.row.col.f32.bf16.bf16.f32 "
        "{%0,%1,%2,%3}, {%4,%5,%6,%7}, {%8,%9}, {%0,%1,%2,%3};"
        : "+f"(c[0]), "+f"(c[1]), "+f"(c[2]), "+f"(c[3])
        : "r"(a[0]), "r"(a[1]), "r"(a[2]), "r"(a[3]), "r"(b[0]), "r"(b[1]));
}

// ---------------------------------------------------------------------------
// Kernel 1: classify edges into 8 branches, 2 edges per thread.
// Block-aggregated counting sort, SoA records, in-degree counts.
// ---------------------------------------------------------------------------
__global__ void __launch_bounds__(256) k_classify(
    const float* __restrict__ pos,
    const int* __restrict__ ei,
    const float* __restrict__ ea,
    const float* __restrict__ ew,
    int E)
{
    __shared__ int s_cnt[KB];
    __shared__ int s_base[KB];
    const int t = threadIdx.x;
    if (t < KB) s_cnt[t] = 0;
    __syncthreads();

    const int e0 = blockIdx.x * 512 + t;        // first edge
    const int e1 = e0 + 256;                    // second edge

    int k0 = 0, r0 = 0, s0 = 0, d0 = 0;
    int k1 = 0, r1 = 0, s1 = 0, d1 = 0;
    float4 a0 = make_float4(0.f, 0.f, 0.f, 0.f);
    float4 a1 = make_float4(0.f, 0.f, 0.f, 0.f);
    float w0 = 0.f, w1 = 0.f;

    float2 ps0, pd0, ps1, pd1;
    const bool v0 = (e0 < E), v1 = (e1 < E);
    if (v0) {
        s0 = ei[e0]; d0 = ei[E + e0];
        ps0 = reinterpret_cast<const float2*>(pos)[s0];
        pd0 = reinterpret_cast<const float2*>(pos)[d0];
        a0 = reinterpret_cast<const float4*>(ea)[e0];
        w0 = ew[e0];
    }
    if (v1) {
        s1 = ei[e1]; d1 = ei[E + e1];
        ps1 = reinterpret_cast<const float2*>(pos)[s1];
        pd1 = reinterpret_cast<const float2*>(pos)[d1];
        a1 = reinterpret_cast<const float4*>(ea)[e1];
        w1 = ew[e1];
    }
    if (v0) {
        const float dx = ps0.x - pd0.x, dy = ps0.y - pd0.y;
        k0 = (dx > 0.0f ? 1 : 0) + (dy > 0.0f ? 2 : 0)
           + ((fabsf(dx) - fabsf(dy)) > 0.0f ? 4 : 0);
        r0 = atomicAdd(&s_cnt[k0], 1);
        atomicAdd(&g_cnt[d0], 1);
    }
    if (v1) {
        const float dx = ps1.x - pd1.x, dy = ps1.y - pd1.y;
        k1 = (dx > 0.0f ? 1 : 0) + (dy > 0.0f ? 2 : 0)
           + ((fabsf(dx) - fabsf(dy)) > 0.0f ? 4 : 0);
        r1 = atomicAdd(&s_cnt[k1], 1);
        atomicAdd(&g_cnt[d1], 1);
    }
    __syncthreads();
    if (t < KB) s_base[t] = atomicAdd(&g_bcnt[t], s_cnt[t]);
    __syncthreads();
    if (v0) {
        const int slot = k0 * EMAX + s_base[k0] + r0;
        g_sdp[slot] = ((uint32_t)s0 << 16) | (uint32_t)d0;
        g_eab[slot] = a0;
        g_ewb[slot] = w0;
    }
    if (v1) {
        const int slot = k1 * EMAX + s_base[k1] + r1;
        g_sdp[slot] = ((uint32_t)s1 << 16) | (uint32_t)d1;
        g_eab[slot] = a1;
        g_ewb[slot] = w1;
    }
}

// ---------------------------------------------------------------------------
// Kernel 2: tensor-core precompute: [p0..p7 | skip] = x @ [W1a_0..W1a_7 | Wr]
// ---------------------------------------------------------------------------
__global__ void __launch_bounds__(256) k_precompute_mma(
    const float* __restrict__ x,
    const float* __restrict__ W1,
    const float* __restrict__ Wr,
    int N)
{
    __shared__ uint32_t s_B[PNT * 2 * 32 * 4];   // 36 KB

    for (int idx = threadIdx.x; idx < PNT * 2 * 32; idx += blockDim.x) {
        const int lane = idx & 31, ks = (idx >> 5) & 1, nt = idx >> 6;
        const int cg = lane >> 2, r2 = (lane & 3) * 2;
        const float* src;
        if (nt < 32) src = W1 + ((size_t)(nt >> 2) * CM) * CO + (nt & 3) * 8 + cg;
        else         src = Wr + (nt - 32) * 8 + cg;
        const int r0 = ks * 16 + r2;
        uint32_t h0, l0, h1, l1;
        split2(src[(r0    ) * CO], src[(r0 + 1) * CO], h0, l0);
        split2(src[(r0 + 8) * CO], src[(r0 + 9) * CO], h1, l1);
        uint32_t* dst = &s_B[idx * 4];
        dst[0] = h0; dst[1] = h1; dst[2] = l0; dst[3] = l1;
    }
    __syncthreads();

    const int lane = threadIdx.x & 31;
    const int gid = lane >> 2, tig = lane & 3;
    const int wid = blockIdx.x * (blockDim.x >> 5) + (threadIdx.x >> 5);
    const int nwarp = gridDim.x * (blockDim.x >> 5);
    const int ntile = (N + 31) >> 5;

    for (int tile = wid; tile < ntile; tile += nwarp) {
        const int n0 = (tile << 5) + gid;

        uint32_t Ah[2][2][4], Al[2][2][4];
#pragma unroll
        for (int mt = 0; mt < 2; mt++) {
            const int na = min(n0 + mt * 16, N - 1);
            const int nb = min(n0 + mt * 16 + 8, N - 1);
#pragma unroll
            for (int ks = 0; ks < 2; ks++) {
                const int c0 = ks * 16 + tig * 2;
                float2 v0 = *reinterpret_cast<const float2*>(x + (size_t)na * CI + c0);
                float2 v1 = *reinterpret_cast<const float2*>(x + (size_t)nb * CI + c0);
                float2 v2 = *reinterpret_cast<const float2*>(x + (size_t)na * CI + c0 + 8);
                float2 v3 = *reinterpret_cast<const float2*>(x + (size_t)nb * CI + c0 + 8);
                split2(v0.x, v0.y, Ah[mt][ks][0], Al[mt][ks][0]);
                split2(v1.x, v1.y, Ah[mt][ks][1], Al[mt][ks][1]);
                split2(v2.x, v2.y, Ah[mt][ks][2], Al[mt][ks][2]);
                split2(v3.x, v3.y, Ah[mt][ks][3], Al[mt][ks][3]);
            }
        }

#pragma unroll
        for (int nt = 0; nt < PNT; nt++) {
            float c[2][4] = {{0.f,0.f,0.f,0.f},{0.f,0.f,0.f,0.f}};
#pragma unroll
            for (int ks = 0; ks < 2; ks++) {
                const uint4 bq = *reinterpret_cast<const uint4*>(
                    &s_B[((nt * 2 + ks) * 32 + lane) * 4]);
                uint32_t bh[2] = {bq.x, bq.y};
                uint32_t bl[2] = {bq.z, bq.w};
#pragma unroll
                for (int mt = 0; mt < 2; mt++) {
                    mma_bf16(c[mt], Ah[mt][ks], bh);
                    mma_bf16(c[mt], Al[mt][ks], bh);
                    mma_bf16(c[mt], Ah[mt][ks], bl);
                }
            }
            float* base;
            int ch;
            if (nt < 32) { base = g_p + (size_t)(nt >> 2) * N * CO; ch = (nt & 3) * 8 + tig * 2; }
            else         { base = g_skip;                            ch = (nt - 32) * 8 + tig * 2; }
#pragma unroll
            for (int mt = 0; mt < 2; mt++) {
                const int na = n0 + mt * 16;
                if (na < N)
                    *reinterpret_cast<float2*>(base + (size_t)na * CO + ch) =
                        make_float2(c[mt][0], c[mt][1]);
                if (na + 8 < N)
                    *reinterpret_cast<float2*>(base + (size_t)(na + 8) * CO + ch) =
                        make_float2(c[mt][2], c[mt][3]);
            }
        }
    }
}

// ---------------------------------------------------------------------------
// Kernel 3: warp-tile edge MLP (FROZEN body; launch = exactly one resident
// wave: 74 blocks/branch x 8 branches = 592 blocks = 4/SM x 148 SMs).
// ---------------------------------------------------------------------------
#define WPB 4   // warps per block
__global__ void __launch_bounds__(32 * WPB, 4) k_edge_mlp(
    const float* __restrict__ W1,
    const float* __restrict__ b1,
    const float* __restrict__ W2,
    const float* __restrict__ b2,
    int N)
{
    const int k    = blockIdx.y;
    const int lane = threadIdx.x & 31;
    const int w    = threadIdx.x >> 5;

    __shared__ float  s_h[WPB][32][TS];    // h tile / C transpose buffer
    __shared__ float4 s_ea[WPB][32];
    __shared__ float  s_ew[WPB][32];
    __shared__ int    s_d[WPB][32];

    // ---- per-lane layer-1 tail weights (channels j*4..j*4+3) ----
    const int j = lane & 7;
    float4 w1b[4];
#pragma unroll
    for (int q = 0; q < 4; q++)
        w1b[q] = *reinterpret_cast<const float4*>(
            W1 + ((size_t)k * CM + 32 + q) * CO + j * 4);
    const float4 b1v = *reinterpret_cast<const float4*>(b1 + k * CO + j * 4);

    // ---- B fragments (W2), bf16 hi/lo, register-resident ----
    uint32_t Bh[4][2][2], Bl[4][2][2];
    {
        const int col = lane >> 2;
        const int r2  = (lane & 3) * 2;
        const float* W2k = W2 + (size_t)k * CO * CO;
#pragma unroll
        for (int nt = 0; nt < 4; nt++)
#pragma unroll
            for (int ks = 0; ks < 2; ks++) {
                const int r0 = ks * 16 + r2;
                split2(W2k[(r0    ) * CO + nt * 8 + col],
                       W2k[(r0 + 1) * CO + nt * 8 + col],
                       Bh[nt][ks][0], Bl[nt][ks][0]);
                split2(W2k[(r0 + 8) * CO + nt * 8 + col],
                       W2k[(r0 + 9) * CO + nt * 8 + col],
                       Bh[nt][ks][1], Bl[nt][ks][1]);
            }
    }
    float2 b2v[4];
#pragma unroll
    for (int nt = 0; nt < 4; nt++)
        b2v[nt] = *reinterpret_cast<const float2*>(
            b2 + k * CO + nt * 8 + 2 * (lane & 3));

    const int cnt = g_bcnt[k];
    const int ntile = (cnt + 31) >> 5;
    const uint32_t* __restrict__ sdp = g_sdp + (size_t)k * EMAX;
    const float4*   __restrict__ eab = g_eab + (size_t)k * EMAX;
    const float*    __restrict__ ewb = g_ewb + (size_t)k * EMAX;
    const float4*   __restrict__ pb =
        reinterpret_cast<const float4*>(g_p + (size_t)k * N * CO);

    const int gwarp = blockIdx.x * WPB + w;
    const int nwarp = gridDim.x * WPB;

    for (int tile = gwarp; tile < ntile; tile += nwarp) {
        const int idx = (tile << 5) + lane;
        int si = 0, di = 0;
        float ewv = 0.f;
        float4 ea = make_float4(0.f, 0.f, 0.f, 0.f);
        if (idx < cnt) {
            const uint32_t p = sdp[idx];
            si = (int)(p >> 16);
            di = (int)(p & 0xffffu);
            ea = eab[idx];
            ewv = ewb[idx];
        }
        s_ea[w][lane] = ea;
        s_ew[w][lane] = ewv;
        s_d[w][lane]  = di;
        __syncwarp();

        // ---- cooperative gather + fused layer 1 ----
        const int g = lane >> 3;
#pragma unroll
        for (int i = 0; i < 8; i++) {
            const int t = i * 4 + g;
            const int ss = __shfl_sync(0xffffffffu, si, t);
            const int dd = __shfl_sync(0xffffffffu, di, t);
            const float4 a  = pb[ss * 8 + j];
            const float4 b  = pb[dd * 8 + j];
            const float4 et = s_ea[w][t];
            float4 h4;
            h4.x = fmaf(et.x, w1b[0].x, fmaf(et.y, w1b[1].x,
                   fmaf(et.z, w1b[2].x, fmaf(et.w, w1b[3].x, b1v.x + a.x - b.x))));
            h4.y = fmaf(et.x, w1b[0].y, fmaf(et.y, w1b[1].y,
                   fmaf(et.z, w1b[2].y, fmaf(et.w, w1b[3].y, b1v.y + a.y - b.y))));
            h4.z = fmaf(et.x, w1b[0].z, fmaf(et.y, w1b[1].z,
                   fmaf(et.z, w1b[2].z, fmaf(et.w, w1b[3].z, b1v.z + a.z - b.z))));
            h4.w = fmaf(et.x, w1b[0].w, fmaf(et.y, w1b[1].w,
                   fmaf(et.z, w1b[2].w, fmaf(et.w, w1b[3].w, b1v.w + a.w - b.w))));
            h4.x = fmaxf(h4.x, 0.f);
            h4.y = fmaxf(h4.y, 0.f);
            h4.z = fmaxf(h4.z, 0.f);
            h4.w = fmaxf(h4.w, 0.f);
            *reinterpret_cast<float4*>(&s_h[w][t][j * 4]) = h4;
        }
        __syncwarp();

        // ---- layer 2: bf16 MMA (2 mt x 4 nt x 2 ks x 3 terms) ----
#pragma unroll
        for (int mt = 0; mt < 2; mt++) {
            const int ra = mt * 16 + (lane >> 2);
            const int rb = ra + 8;
            const int c2 = (lane & 3) * 2;
            uint32_t Ah[2][4], Al[2][4];
#pragma unroll
            for (int ks = 0; ks < 2; ks++) {
                const int k0 = ks * 16 + c2;
                float2 v0 = *reinterpret_cast<const float2*>(&s_h[w][ra][k0]);
                float2 v1 = *reinterpret_cast<const float2*>(&s_h[w][rb][k0]);
                float2 v2 = *reinterpret_cast<const float2*>(&s_h[w][ra][k0 + 8]);
                float2 v3 = *reinterpret_cast<const float2*>(&s_h[w][rb][k0 + 8]);
                split2(v0.x, v0.y, Ah[ks][0], Al[ks][0]);
                split2(v1.x, v1.y, Ah[ks][1], Al[ks][1]);
                split2(v2.x, v2.y, Ah[ks][2], Al[ks][2]);
                split2(v3.x, v3.y, Ah[ks][3], Al[ks][3]);
            }
            const float ewa = s_ew[w][ra];
            const float ewb2 = s_ew[w][rb];
#pragma unroll
            for (int nt = 0; nt < 4; nt++) {
                float c[4] = {0.f, 0.f, 0.f, 0.f};
#pragma unroll
                for (int ks = 0; ks < 2; ks++) {
                    mma_bf16(c, Ah[ks], Bh[nt][ks]);
                    mma_bf16(c, Al[ks], Bh[nt][ks]);
                    mma_bf16(c, Ah[ks], Bl[nt][ks]);
                }
                float2 fa, fb;
                fa.x = fmaxf(c[0] + b2v[nt].x, 0.f) * ewa;
                fa.y = fmaxf(c[1] + b2v[nt].y, 0.f) * ewa;
                fb.x = fmaxf(c[2] + b2v[nt].x, 0.f) * ewb2;
                fb.y = fmaxf(c[3] + b2v[nt].y, 0.f) * ewb2;
                *reinterpret_cast<float2*>(&s_h[w][ra][nt * 8 + c2]) = fa;
                *reinterpret_cast<float2*>(&s_h[w][rb][nt * 8 + c2]) = fb;
            }
        }
        __syncwarp();

        // ---- coalesced scatter: one full edge row per 8 lanes, red.v4 ----
        const int c4 = (lane & 7) * 4;
#pragma unroll
        for (int i = 0; i < 8; i++) {
            const int r = i * 4 + (lane >> 3);
            const float4 v = *reinterpret_cast<const float4*>(&s_h[w][r][c4]);
            float* dst = g_acc + (size_t)s_d[w][r] * CO + c4;
            asm volatile("red.global.add.v4.f32 [%0], {%1, %2, %3, %4};"
                         :: "l"(dst), "f"(v.x), "f"(v.y), "f"(v.z), "f"(v.w)
                         : "memory");
        }
        __syncwarp();
    }
}

// ---------------------------------------------------------------------------
// Kernel 4: out = acc / max(cnt,1) + skip + br, then SELF-CLEAN the scratch
// (g_acc, g_cnt, g_bcnt). Proven round-12 form (1 float4 per thread).
// ---------------------------------------------------------------------------
__global__ void __launch_bounds__(256) k_finalize(
    float* __restrict__ out, const float* __restrict__ br, int N)
{
    const int i = blockIdx.x * blockDim.x + threadIdx.x;   // over N*8 float4s
    if (i >= N * 8) return;
    const int n = i >> 3;
    const float inv = 1.0f / fmaxf((float)g_cnt[n], 1.0f);
    const float4 a = reinterpret_cast<const float4*>(g_acc)[i];
    const float4 s = reinterpret_cast<const float4*>(g_skip)[i];
    const float4 b = reinterpret_cast<const float4*>(br)[i & 7];
    float4 o;
    o.x = fmaf(a.x, inv, s.x + b.x);
    o.y = fmaf(a.y, inv, s.y + b.y);
    o.z = fmaf(a.z, inv, s.z + b.z);
    o.w = fmaf(a.w, inv, s.w + b.w);
    reinterpret_cast<float4*>(out)[i] = o;

    // self-clean for next replay
    reinterpret_cast<float4*>(g_acc)[i] = make_float4(0.f, 0.f, 0.f, 0.f);
    if ((i & 7) == 0) g_cnt[n] = 0;
    if (i < KB) g_bcnt[i] = 0;
}

// ---------------------------------------------------------------------------
// Host launcher
// ---------------------------------------------------------------------------
extern "C" void kernel_launch(void* const* d_in, const int* in_sizes, int n_in,
                              void* d_out, int out_size)
{
    const float* x    = (const float*)d_in[0];   // [N, 32]
    const float* pos  = (const float*)d_in[1];   // [N, 2]
    const int*   ei   = (const int*)  d_in[2];   // [2, E]
    const float* ea   = (const float*)d_in[3];   // [E, 4]
    const float* ew   = (const float*)d_in[4];   // [E]
    const float* W1   = (const float*)d_in[5];   // [8, 36, 32]
    const float* b1   = (const float*)d_in[6];   // [8, 32]
    const float* W2   = (const float*)d_in[7];   // [8, 32, 32]
    const float* b2   = (const float*)d_in[8];   // [8, 32]
    const float* Wr   = (const float*)d_in[9];   // [32, 32]
    const float* br   = (const float*)d_in[10];  // [32]
    float* out = (float*)d_out;

    const int N = in_sizes[0] / CI;
    const int E = in_sizes[4];

    // 1) classify: counting sort into 8 branches, 2 edges/thread
    k_classify<<<(E + 511) / 512, 256>>>(pos, ei, ea, ew, E);

    // 2) tensor-core precompute: p[0..7] and skip in one GEMM
    {
        const int ntile = (N + 31) / 32;
        const int blocks = (ntile + 7) / 8;    // 8 warps per block
        k_precompute_mma<<<blocks, 256>>>(x, W1, Wr, N);
    }

    // 3) warp-tile edge MLP: exactly one resident wave (74*8 = 592 = 4*148)
    {
        dim3 grid(74, KB);
        k_edge_mlp<<<grid, 32 * WPB>>>(W1, b1, W2, b2, N);
    }

    // 4) mean + skip connection (+ br) + scratch self-clean
    k_finalize<<<(N * 8 + 255) / 256, 256>>>(out, br, N);
}

// round 17
// speedup vs baseline: 1.1273x; 1.0695x over previous
#include <cuda_runtime.h>
#include <cstdint>

#define NMAX 50000
#define EMAX 800000
#define KB 8          // branches
#define CI 32
#define CO 32
#define CM 36         // C_IN + 4
#define TS 36         // h-tile row stride (floats)
#define PNT 36        // precompute n-tiles: 8 branches*4 + skip*4

// scratch (device globals; allocation is forbidden).
// g_acc / g_cnt / g_bcnt are BSS-zeroed at module load and then self-cleaned
// by k_finalize at the end of every launch -> no zeroing kernel needed.
__device__ float    g_acc[NMAX * CO];        // per-node accumulated edge features
__device__ float    g_skip[NMAX * CO];       // x @ Wr (br folded into finalize)
__device__ float    g_p[KB * NMAX * CO];     // per-branch x @ W1a
__device__ int      g_cnt[NMAX];             // in-degree
__device__ uint32_t g_sdp[KB * EMAX];        // packed {s:16, d:16} per branch slot
__device__ float4   g_eab[KB * EMAX];        // edge_attr per branch slot
__device__ float    g_ewb[KB * EMAX];        // edge_weight per branch slot
__device__ int      g_bcnt[KB];

// ---------------------------------------------------------------------------
// helpers: bf16 hi/lo split + bf16 mma
// ---------------------------------------------------------------------------
__device__ __forceinline__ void split2(float x0, float x1,
                                       uint32_t& hi, uint32_t& lo) {
    uint32_t h;
    asm("cvt.rn.bf16x2.f32 %0, %1, %2;" : "=r"(h) : "f"(x1), "f"(x0)); // lo=x0
    const float h0 = __uint_as_float(h << 16);
    const float h1 = __uint_as_float(h & 0xffff0000u);
    const float l0 = x0 - h0;
    const float l1 = x1 - h1;
    uint32_t l;
    asm("cvt.rn.bf16x2.f32 %0, %1, %2;" : "=r"(l) : "f"(l1), "f"(l0));
    hi = h; lo = l;
}
__device__ __forceinline__ void mma_bf16(float c[4], const uint32_t a[4],
                                         const uint32_t b[2]) {
    asm volatile(
        "mma.sync.aligned.m16n8k16.row.col.f32.bf16.bf16.f32 "
        "{%0,%1,%2,%3}, {%4,%5,%6,%7}, {%8,%9}, {%0,%1,%2,%3};"
        : "+f"(c[0]), "+f"(c[1]), "+f"(c[2]), "+f"(c[3])
        : "r"(a[0]), "r"(a[1]), "r"(a[2]), "r"(a[3]), "r"(b[0]), "r"(b[1]));
}

// ---------------------------------------------------------------------------
// Kernel 1: classify edges into 8 branches, 2 edges per thread.
// Triggers programmatic launch completion immediately so the independent
// precompute kernel can co-schedule (PDL overlap).
// ---------------------------------------------------------------------------
__global__ void __launch_bounds__(256) k_classify(
    const float* __restrict__ pos,
    const int* __restrict__ ei,
    const float* __restrict__ ea,
    const float* __restrict__ ew,
    int E)
{
#if __CUDA_ARCH__ >= 900
    cudaTriggerProgrammaticLaunchCompletion();
#endif
    __shared__ int s_cnt[KB];
    __shared__ int s_base[KB];
    const int t = threadIdx.x;
    if (t < KB) s_cnt[t] = 0;
    __syncthreads();

    const int e0 = blockIdx.x * 512 + t;        // first edge
    const int e1 = e0 + 256;                    // second edge

    int k0 = 0, r0 = 0, s0 = 0, d0 = 0;
    int k1 = 0, r1 = 0, s1 = 0, d1 = 0;
    float4 a0 = make_float4(0.f, 0.f, 0.f, 0.f);
    float4 a1 = make_float4(0.f, 0.f, 0.f, 0.f);
    float w0 = 0.f, w1 = 0.f;

    float2 ps0, pd0, ps1, pd1;
    const bool v0 = (e0 < E), v1 = (e1 < E);
    if (v0) {
        s0 = ei[e0]; d0 = ei[E + e0];
        ps0 = reinterpret_cast<const float2*>(pos)[s0];
        pd0 = reinterpret_cast<const float2*>(pos)[d0];
        a0 = reinterpret_cast<const float4*>(ea)[e0];
        w0 = ew[e0];
    }
    if (v1) {
        s1 = ei[e1]; d1 = ei[E + e1];
        ps1 = reinterpret_cast<const float2*>(pos)[s1];
        pd1 = reinterpret_cast<const float2*>(pos)[d1];
        a1 = reinterpret_cast<const float4*>(ea)[e1];
        w1 = ew[e1];
    }
    if (v0) {
        const float dx = ps0.x - pd0.x, dy = ps0.y - pd0.y;
        k0 = (dx > 0.0f ? 1 : 0) + (dy > 0.0f ? 2 : 0)
           + ((fabsf(dx) - fabsf(dy)) > 0.0f ? 4 : 0);
        r0 = atomicAdd(&s_cnt[k0], 1);
        atomicAdd(&g_cnt[d0], 1);
    }
    if (v1) {
        const float dx = ps1.x - pd1.x, dy = ps1.y - pd1.y;
        k1 = (dx > 0.0f ? 1 : 0) + (dy > 0.0f ? 2 : 0)
           + ((fabsf(dx) - fabsf(dy)) > 0.0f ? 4 : 0);
        r1 = atomicAdd(&s_cnt[k1], 1);
        atomicAdd(&g_cnt[d1], 1);
    }
    __syncthreads();
    if (t < KB) s_base[t] = atomicAdd(&g_bcnt[t], s_cnt[t]);
    __syncthreads();
    if (v0) {
        const int slot = k0 * EMAX + s_base[k0] + r0;
        g_sdp[slot] = ((uint32_t)s0 << 16) | (uint32_t)d0;
        g_eab[slot] = a0;
        g_ewb[slot] = w0;
    }
    if (v1) {
        const int slot = k1 * EMAX + s_base[k1] + r1;
        g_sdp[slot] = ((uint32_t)s1 << 16) | (uint32_t)d1;
        g_eab[slot] = a1;
        g_ewb[slot] = w1;
    }
}

// ---------------------------------------------------------------------------
// Kernel 2: tensor-core precompute: [p0..p7 | skip] = x @ [W1a_0..W1a_7 | Wr]
// Launched with PDL so it overlaps the independent classify kernel.
// ---------------------------------------------------------------------------
__global__ void __launch_bounds__(256) k_precompute_mma(
    const float* __restrict__ x,
    const float* __restrict__ W1,
    const float* __restrict__ Wr,
    int N)
{
    __shared__ uint32_t s_B[PNT * 2 * 32 * 4];   // 36 KB

    for (int idx = threadIdx.x; idx < PNT * 2 * 32; idx += blockDim.x) {
        const int lane = idx & 31, ks = (idx >> 5) & 1, nt = idx >> 6;
        const int cg = lane >> 2, r2 = (lane & 3) * 2;
        const float* src;
        if (nt < 32) src = W1 + ((size_t)(nt >> 2) * CM) * CO + (nt & 3) * 8 + cg;
        else         src = Wr + (nt - 32) * 8 + cg;
        const int r0 = ks * 16 + r2;
        uint32_t h0, l0, h1, l1;
        split2(src[(r0    ) * CO], src[(r0 + 1) * CO], h0, l0);
        split2(src[(r0 + 8) * CO], src[(r0 + 9) * CO], h1, l1);
        uint32_t* dst = &s_B[idx * 4];
        dst[0] = h0; dst[1] = h1; dst[2] = l0; dst[3] = l1;
    }
    __syncthreads();

    const int lane = threadIdx.x & 31;
    const int gid = lane >> 2, tig = lane & 3;
    const int wid = blockIdx.x * (blockDim.x >> 5) + (threadIdx.x >> 5);
    const int nwarp = gridDim.x * (blockDim.x >> 5);
    const int ntile = (N + 31) >> 5;

    for (int tile = wid; tile < ntile; tile += nwarp) {
        const int n0 = (tile << 5) + gid;

        uint32_t Ah[2][2][4], Al[2][2][4];
#pragma unroll
        for (int mt = 0; mt < 2; mt++) {
            const int na = min(n0 + mt * 16, N - 1);
            const int nb = min(n0 + mt * 16 + 8, N - 1);
#pragma unroll
            for (int ks = 0; ks < 2; ks++) {
                const int c0 = ks * 16 + tig * 2;
                float2 v0 = *reinterpret_cast<const float2*>(x + (size_t)na * CI + c0);
                float2 v1 = *reinterpret_cast<const float2*>(x + (size_t)nb * CI + c0);
                float2 v2 = *reinterpret_cast<const float2*>(x + (size_t)na * CI + c0 + 8);
                float2 v3 = *reinterpret_cast<const float2*>(x + (size_t)nb * CI + c0 + 8);
                split2(v0.x, v0.y, Ah[mt][ks][0], Al[mt][ks][0]);
                split2(v1.x, v1.y, Ah[mt][ks][1], Al[mt][ks][1]);
                split2(v2.x, v2.y, Ah[mt][ks][2], Al[mt][ks][2]);
                split2(v3.x, v3.y, Ah[mt][ks][3], Al[mt][ks][3]);
            }
        }

#pragma unroll
        for (int nt = 0; nt < PNT; nt++) {
            float c[2][4] = {{0.f,0.f,0.f,0.f},{0.f,0.f,0.f,0.f}};
#pragma unroll
            for (int ks = 0; ks < 2; ks++) {
                const uint4 bq = *reinterpret_cast<const uint4*>(
                    &s_B[((nt * 2 + ks) * 32 + lane) * 4]);
                uint32_t bh[2] = {bq.x, bq.y};
                uint32_t bl[2] = {bq.z, bq.w};
#pragma unroll
                for (int mt = 0; mt < 2; mt++) {
                    mma_bf16(c[mt], Ah[mt][ks], bh);
                    mma_bf16(c[mt], Al[mt][ks], bh);
                    mma_bf16(c[mt], Ah[mt][ks], bl);
                }
            }
            float* base;
            int ch;
            if (nt < 32) { base = g_p + (size_t)(nt >> 2) * N * CO; ch = (nt & 3) * 8 + tig * 2; }
            else         { base = g_skip;                            ch = (nt - 32) * 8 + tig * 2; }
#pragma unroll
            for (int mt = 0; mt < 2; mt++) {
                const int na = n0 + mt * 16;
                if (na < N)
                    *reinterpret_cast<float2*>(base + (size_t)na * CO + ch) =
                        make_float2(c[mt][0], c[mt][1]);
                if (na + 8 < N)
                    *reinterpret_cast<float2*>(base + (size_t)(na + 8) * CO + ch) =
                        make_float2(c[mt][2], c[mt][3]);
            }
        }
    }
}

// ---------------------------------------------------------------------------
// Kernel 3: warp-tile edge MLP (FROZEN body; one resident wave: 74x8=592).
// ---------------------------------------------------------------------------
#define WPB 4   // warps per block
__global__ void __launch_bounds__(32 * WPB, 4) k_edge_mlp(
    const float* __restrict__ W1,
    const float* __restrict__ b1,
    const float* __restrict__ W2,
    const float* __restrict__ b2,
    int N)
{
    const int k    = blockIdx.y;
    const int lane = threadIdx.x & 31;
    const int w    = threadIdx.x >> 5;

    __shared__ float  s_h[WPB][32][TS];    // h tile / C transpose buffer
    __shared__ float4 s_ea[WPB][32];
    __shared__ float  s_ew[WPB][32];
    __shared__ int    s_d[WPB][32];

    // ---- per-lane layer-1 tail weights (channels j*4..j*4+3) ----
    const int j = lane & 7;
    float4 w1b[4];
#pragma unroll
    for (int q = 0; q < 4; q++)
        w1b[q] = *reinterpret_cast<const float4*>(
            W1 + ((size_t)k * CM + 32 + q) * CO + j * 4);
    const float4 b1v = *reinterpret_cast<const float4*>(b1 + k * CO + j * 4);

    // ---- B fragments (W2), bf16 hi/lo, register-resident ----
    uint32_t Bh[4][2][2], Bl[4][2][2];
    {
        const int col = lane >> 2;
        const int r2  = (lane & 3) * 2;
        const float* W2k = W2 + (size_t)k * CO * CO;
#pragma unroll
        for (int nt = 0; nt < 4; nt++)
#pragma unroll
            for (int ks = 0; ks < 2; ks++) {
                const int r0 = ks * 16 + r2;
                split2(W2k[(r0    ) * CO + nt * 8 + col],
                       W2k[(r0 + 1) * CO + nt * 8 + col],
                       Bh[nt][ks][0], Bl[nt][ks][0]);
                split2(W2k[(r0 + 8) * CO + nt * 8 + col],
                       W2k[(r0 + 9) * CO + nt * 8 + col],
                       Bh[nt][ks][1], Bl[nt][ks][1]);
            }
    }
    float2 b2v[4];
#pragma unroll
    for (int nt = 0; nt < 4; nt++)
        b2v[nt] = *reinterpret_cast<const float2*>(
            b2 + k * CO + nt * 8 + 2 * (lane & 3));

    const int cnt = g_bcnt[k];
    const int ntile = (cnt + 31) >> 5;
    const uint32_t* __restrict__ sdp = g_sdp + (size_t)k * EMAX;
    const float4*   __restrict__ eab = g_eab + (size_t)k * EMAX;
    const float*    __restrict__ ewb = g_ewb + (size_t)k * EMAX;
    const float4*   __restrict__ pb =
        reinterpret_cast<const float4*>(g_p + (size_t)k * N * CO);

    const int gwarp = blockIdx.x * WPB + w;
    const int nwarp = gridDim.x * WPB;

    for (int tile = gwarp; tile < ntile; tile += nwarp) {
        const int idx = (tile << 5) + lane;
        int si = 0, di = 0;
        float ewv = 0.f;
        float4 ea = make_float4(0.f, 0.f, 0.f, 0.f);
        if (idx < cnt) {
            const uint32_t p = sdp[idx];
            si = (int)(p >> 16);
            di = (int)(p & 0xffffu);
            ea = eab[idx];
            ewv = ewb[idx];
        }
        s_ea[w][lane] = ea;
        s_ew[w][lane] = ewv;
        s_d[w][lane]  = di;
        __syncwarp();

        // ---- cooperative gather + fused layer 1 ----
        const int g = lane >> 3;
#pragma unroll
        for (int i = 0; i < 8; i++) {
            const int t = i * 4 + g;
            const int ss = __shfl_sync(0xffffffffu, si, t);
            const int dd = __shfl_sync(0xffffffffu, di, t);
            const float4 a  = pb[ss * 8 + j];
            const float4 b  = pb[dd * 8 + j];
            const float4 et = s_ea[w][t];
            float4 h4;
            h4.x = fmaf(et.x, w1b[0].x, fmaf(et.y, w1b[1].x,
                   fmaf(et.z, w1b[2].x, fmaf(et.w, w1b[3].x, b1v.x + a.x - b.x))));
            h4.y = fmaf(et.x, w1b[0].y, fmaf(et.y, w1b[1].y,
                   fmaf(et.z, w1b[2].y, fmaf(et.w, w1b[3].y, b1v.y + a.y - b.y))));
            h4.z = fmaf(et.x, w1b[0].z, fmaf(et.y, w1b[1].z,
                   fmaf(et.z, w1b[2].z, fmaf(et.w, w1b[3].z, b1v.z + a.z - b.z))));
            h4.w = fmaf(et.x, w1b[0].w, fmaf(et.y, w1b[1].w,
                   fmaf(et.z, w1b[2].w, fmaf(et.w, w1b[3].w, b1v.w + a.w - b.w))));
            h4.x = fmaxf(h4.x, 0.f);
            h4.y = fmaxf(h4.y, 0.f);
            h4.z = fmaxf(h4.z, 0.f);
            h4.w = fmaxf(h4.w, 0.f);
            *reinterpret_cast<float4*>(&s_h[w][t][j * 4]) = h4;
        }
        __syncwarp();

        // ---- layer 2: bf16 MMA (2 mt x 4 nt x 2 ks x 3 terms) ----
#pragma unroll
        for (int mt = 0; mt < 2; mt++) {
            const int ra = mt * 16 + (lane >> 2);
            const int rb = ra + 8;
            const int c2 = (lane & 3) * 2;
            uint32_t Ah[2][4], Al[2][4];
#pragma unroll
            for (int ks = 0; ks < 2; ks++) {
                const int k0 = ks * 16 + c2;
                float2 v0 = *reinterpret_cast<const float2*>(&s_h[w][ra][k0]);
                float2 v1 = *reinterpret_cast<const float2*>(&s_h[w][rb][k0]);
                float2 v2 = *reinterpret_cast<const float2*>(&s_h[w][ra][k0 + 8]);
                float2 v3 = *reinterpret_cast<const float2*>(&s_h[w][rb][k0 + 8]);
                split2(v0.x, v0.y, Ah[ks][0], Al[ks][0]);
                split2(v1.x, v1.y, Ah[ks][1], Al[ks][1]);
                split2(v2.x, v2.y, Ah[ks][2], Al[ks][2]);
                split2(v3.x, v3.y, Ah[ks][3], Al[ks][3]);
            }
            const float ewa = s_ew[w][ra];
            const float ewb2 = s_ew[w][rb];
#pragma unroll
            for (int nt = 0; nt < 4; nt++) {
                float c[4] = {0.f, 0.f, 0.f, 0.f};
#pragma unroll
                for (int ks = 0; ks < 2; ks++) {
                    mma_bf16(c, Ah[ks], Bh[nt][ks]);
                    mma_bf16(c, Al[ks], Bh[nt][ks]);
                    mma_bf16(c, Ah[ks], Bl[nt][ks]);
                }
                float2 fa, fb;
                fa.x = fmaxf(c[0] + b2v[nt].x, 0.f) * ewa;
                fa.y = fmaxf(c[1] + b2v[nt].y, 0.f) * ewa;
                fb.x = fmaxf(c[2] + b2v[nt].x, 0.f) * ewb2;
                fb.y = fmaxf(c[3] + b2v[nt].y, 0.f) * ewb2;
                *reinterpret_cast<float2*>(&s_h[w][ra][nt * 8 + c2]) = fa;
                *reinterpret_cast<float2*>(&s_h[w][rb][nt * 8 + c2]) = fb;
            }
        }
        __syncwarp();

        // ---- coalesced scatter: one full edge row per 8 lanes, red.v4 ----
        const int c4 = (lane & 7) * 4;
#pragma unroll
        for (int i = 0; i < 8; i++) {
            const int r = i * 4 + (lane >> 3);
            const float4 v = *reinterpret_cast<const float4*>(&s_h[w][r][c4]);
            float* dst = g_acc + (size_t)s_d[w][r] * CO + c4;
            asm volatile("red.global.add.v4.f32 [%0], {%1, %2, %3, %4};"
                         :: "l"(dst), "f"(v.x), "f"(v.y), "f"(v.z), "f"(v.w)
                         : "memory");
        }
        __syncwarp();
    }
}

// ---------------------------------------------------------------------------
// Kernel 4: out = acc / max(cnt,1) + skip + br, then SELF-CLEAN the scratch
// (g_acc, g_cnt, g_bcnt). Proven round-12 form (1 float4 per thread).
// ---------------------------------------------------------------------------
__global__ void __launch_bounds__(256) k_finalize(
    float* __restrict__ out, const float* __restrict__ br, int N)
{
    const int i = blockIdx.x * blockDim.x + threadIdx.x;   // over N*8 float4s
    if (i >= N * 8) return;
    const int n = i >> 3;
    const float inv = 1.0f / fmaxf((float)g_cnt[n], 1.0f);
    const float4 a = reinterpret_cast<const float4*>(g_acc)[i];
    const float4 s = reinterpret_cast<const float4*>(g_skip)[i];
    const float4 b = reinterpret_cast<const float4*>(br)[i & 7];
    float4 o;
    o.x = fmaf(a.x, inv, s.x + b.x);
    o.y = fmaf(a.y, inv, s.y + b.y);
    o.z = fmaf(a.z, inv, s.z + b.z);
    o.w = fmaf(a.w, inv, s.w + b.w);
    reinterpret_cast<float4*>(out)[i] = o;

    // self-clean for next replay
    reinterpret_cast<float4*>(g_acc)[i] = make_float4(0.f, 0.f, 0.f, 0.f);
    if ((i & 7) == 0) g_cnt[n] = 0;
    if (i < KB) g_bcnt[i] = 0;
}

// ---------------------------------------------------------------------------
// Host launcher
// ---------------------------------------------------------------------------
extern "C" void kernel_launch(void* const* d_in, const int* in_sizes, int n_in,
                              void* d_out, int out_size)
{
    const float* x    = (const float*)d_in[0];   // [N, 32]
    const float* pos  = (const float*)d_in[1];   // [N, 2]
    const int*   ei   = (const int*)  d_in[2];   // [2, E]
    const float* ea   = (const float*)d_in[3];   // [E, 4]
    const float* ew   = (const float*)d_in[4];   // [E]
    const float* W1   = (const float*)d_in[5];   // [8, 36, 32]
    const float* b1   = (const float*)d_in[6];   // [8, 32]
    const float* W2   = (const float*)d_in[7];   // [8, 32, 32]
    const float* b2   = (const float*)d_in[8];   // [8, 32]
    const float* Wr   = (const float*)d_in[9];   // [32, 32]
    const float* br   = (const float*)d_in[10];  // [32]
    float* out = (float*)d_out;

    const int N = in_sizes[0] / CI;
    const int E = in_sizes[4];

    // 1) classify (triggers programmatic launch completion at block start)
    k_classify<<<(E + 511) / 512, 256>>>(pos, ei, ea, ew, E);

    // 2) precompute, PDL-overlapped with classify (independent data)
    {
        const int ntile = (N + 31) / 32;
        const int blocks = (ntile + 7) / 8;    // 8 warps per block

        cudaLaunchConfig_t cfg = {};
        cfg.gridDim  = dim3(blocks, 1, 1);
        cfg.blockDim = dim3(256, 1, 1);
        cudaLaunchAttribute attr[1];
        attr[0].id = cudaLaunchAttributeProgrammaticStreamSerialization;
        attr[0].val.programmaticStreamSerializationAllowed = 1;
        cfg.attrs = attr;
        cfg.numAttrs = 1;
        cudaLaunchKernelEx(&cfg, k_precompute_mma, x, W1, Wr, N);
    }

    // 3) warp-tile edge MLP (normal launch -> waits for BOTH classify and
    //    precompute); one resident wave (74*8 = 592 = 4*148)
    {
        dim3 grid(74, KB);
        k_edge_mlp<<<grid, 32 * WPB>>>(W1, b1, W2, b2, N);
    }

    // 4) mean + skip connection (+ br) + scratch self-clean
    k_finalize<<<(N * 8 + 255) / 256, 256>>>(out, br, N);
}